// round 9
// baseline (speedup 1.0000x reference)
#include <cuda_runtime.h>
#include <cstdint>

#define BSZ 32
#define NPIX 13107200
#define HW4 102400            // float4 units per channel-plane per batch
#define HW8 51200             // 8-pixel chunks per batch
#define NCHUNK 1638400        // NPIX/8 total 8-pixel chunks
#define NB 32768              // full bf16-code histogram (15-bit codes)
#define GRID_H 152            // persistent: 1 block per SM
#define THR_H 768
#define STRIDE_H (GRID_H*THR_H)
#define THR_F 1024
#define NSEG 8                // k_final segments (4096 codes each)

typedef unsigned long long u64;

// -------- device state (zero-init at load; k_final self-cleans) -------
__device__ __align__(16) unsigned int g_hist32[NB];
__device__ double g_pos_loss;
__device__ double g_pos_w;
__device__ unsigned int g_sumPos;

// ---- packed f32x2 helpers ----
__device__ __forceinline__ u64 pk2(float a, float b) {
  u64 r; asm("mov.b64 %0, {%1, %2};" : "=l"(r) : "f"(a), "f"(b)); return r;
}
__device__ __forceinline__ void upk2(u64 v, float& a, float& b) {
  asm("mov.b64 {%0, %1}, %2;" : "=f"(a), "=f"(b) : "l"(v));
}
__device__ __forceinline__ u64 fma2(u64 a, u64 b, u64 c) {
  u64 d; asm("fma.rn.f32x2 %0, %1, %2, %3;" : "=l"(d) : "l"(a), "l"(b), "l"(c)); return d;
}
__device__ __forceinline__ u64 mul2(u64 a, u64 b) {
  u64 d; asm("mul.rn.f32x2 %0, %1, %2;" : "=l"(d) : "l"(a), "l"(b)); return d;
}
__device__ __forceinline__ u64 add2(u64 a, u64 b) {
  u64 d; asm("add.rn.f32x2 %0, %1, %2;" : "=l"(d) : "l"(a), "l"(b)); return d;
}
__device__ __forceinline__ unsigned cvt_bf2(float s0, float s1) {
  unsigned w;
  asm("cvt.rn.satfinite.bf16x2.f32 %0, %1, %2;" : "=r"(w) : "f"(s1), "f"(s0));
  return w;
}
// SAFE bf16-code -> value: inf/NaN codes (>= 0x7F80) map to 0. Counts can
// never land there (cvt is satfinite), so this is exact and keeps the
// unconditional count*value products finite (0 * inf would be NaN).
__device__ __forceinline__ float bf2fs(unsigned code) {
  return (code >= 0x7F80u) ? 0.f : __uint_as_float(code << 16);
}

// ---------------------------------------------------------------
// Single data pass: per-pixel row loss -> bf16 code (positives forced to
// code 0), full 32768-bin count histogram privatized in 128KB dynamic
// smem (1 block/SM, persistent), positive sums block-reduced.
__global__ void __launch_bounds__(THR_H) k_hist(const float4* __restrict__ pr,
                                                const float4* __restrict__ vm,
                                                const float4* __restrict__ wt) {
  extern __shared__ unsigned hist[];          // NB counts
  for (int i = threadIdx.x; i < NB; i += THR_H) hist[i] = 0u;
  __syncthreads();
  const u64 M1 = pk2(-1.f, -1.f);
  u64 pl = 0ull, pw = 0ull;
  unsigned np = 0u;
  for (int c = blockIdx.x * THR_H + threadIdx.x; c < NCHUNK; c += STRIDE_H) {
    int b = c / HW8;
    int i = c - b * HW8;
    int base = 2 * i;
    const float4* prb = pr + (size_t)b * 2 * HW4;
    const float4* vmb = vm + (size_t)b * 2 * HW4;
    const float4* wtb = wt + (size_t)b * HW4;
    float4 p0a = prb[base],       p0b = prb[base + 1];
    float4 p1a = prb[base + HW4], p1b = prb[base + HW4 + 1];
    float4 t0a = vmb[base],       t0b = vmb[base + 1];
    float4 t1a = vmb[base + HW4], t1b = vmb[base + HW4 + 1];
    float4 wa = wtb[base], wb = wtb[base + 1];
    u64 d0 = fma2(pk2(t0a.x, t0a.y), M1, pk2(p0a.x, p0a.y));
    u64 d1 = fma2(pk2(t1a.x, t1a.y), M1, pk2(p1a.x, p1a.y));
    u64 se = fma2(d1, d1, mul2(d0, d0));
    u64 wv = pk2(wa.x, wa.y);
    pl = fma2(se, wv, pl); pw = add2(pw, wv);
    float s0, s1; upk2(se, s0, s1);
    unsigned wA = cvt_bf2(s0, s1);
    if (wa.x > 0.f) { wA &= 0xFFFF0000u; np++; }
    if (wa.y > 0.f) { wA &= 0x0000FFFFu; np++; }
    d0 = fma2(pk2(t0a.z, t0a.w), M1, pk2(p0a.z, p0a.w));
    d1 = fma2(pk2(t1a.z, t1a.w), M1, pk2(p1a.z, p1a.w));
    se = fma2(d1, d1, mul2(d0, d0));
    wv = pk2(wa.z, wa.w);
    pl = fma2(se, wv, pl); pw = add2(pw, wv);
    upk2(se, s0, s1);
    unsigned wB = cvt_bf2(s0, s1);
    if (wa.z > 0.f) { wB &= 0xFFFF0000u; np++; }
    if (wa.w > 0.f) { wB &= 0x0000FFFFu; np++; }
    d0 = fma2(pk2(t0b.x, t0b.y), M1, pk2(p0b.x, p0b.y));
    d1 = fma2(pk2(t1b.x, t1b.y), M1, pk2(p1b.x, p1b.y));
    se = fma2(d1, d1, mul2(d0, d0));
    wv = pk2(wb.x, wb.y);
    pl = fma2(se, wv, pl); pw = add2(pw, wv);
    upk2(se, s0, s1);
    unsigned wC = cvt_bf2(s0, s1);
    if (wb.x > 0.f) { wC &= 0xFFFF0000u; np++; }
    if (wb.y > 0.f) { wC &= 0x0000FFFFu; np++; }
    d0 = fma2(pk2(t0b.z, t0b.w), M1, pk2(p0b.z, p0b.w));
    d1 = fma2(pk2(t1b.z, t1b.w), M1, pk2(p1b.z, p1b.w));
    se = fma2(d1, d1, mul2(d0, d0));
    wv = pk2(wb.z, wb.w);
    pl = fma2(se, wv, pl); pw = add2(pw, wv);
    upk2(se, s0, s1);
    unsigned wD = cvt_bf2(s0, s1);
    if (wb.z > 0.f) { wD &= 0xFFFF0000u; np++; }
    if (wb.w > 0.f) { wD &= 0x0000FFFFu; np++; }
    atomicAdd(&hist[wA & 0xFFFFu], 1u);
    atomicAdd(&hist[wA >> 16], 1u);
    atomicAdd(&hist[wB & 0xFFFFu], 1u);
    atomicAdd(&hist[wB >> 16], 1u);
    atomicAdd(&hist[wC & 0xFFFFu], 1u);
    atomicAdd(&hist[wC >> 16], 1u);
    atomicAdd(&hist[wD & 0xFFFFu], 1u);
    atomicAdd(&hist[wD >> 16], 1u);
  }
  float pl0, pl1, pw0, pw1;
  upk2(pl, pl0, pl1); upk2(pw, pw0, pw1);
  float plf = pl0 + pl1, pwf = pw0 + pw1;
  for (int o = 16; o; o >>= 1) {
    plf += __shfl_down_sync(0xffffffffu, plf, o);
    pwf += __shfl_down_sync(0xffffffffu, pwf, o);
    np  += __shfl_down_sync(0xffffffffu, np, o);
  }
  __shared__ float r_pl[THR_H / 32], r_pw[THR_H / 32];
  __shared__ unsigned r_np[THR_H / 32];
  int wid = threadIdx.x >> 5;
  if ((threadIdx.x & 31u) == 0u) { r_pl[wid] = plf; r_pw[wid] = pwf; r_np[wid] = np; }
  __syncthreads();
  if (threadIdx.x == 0) {
    float bpl = 0.f, bpw = 0.f; unsigned bnp = 0u;
#pragma unroll
    for (int k = 0; k < THR_H / 32; k++) { bpl += r_pl[k]; bpw += r_pw[k]; bnp += r_np[k]; }
    if (bpl != 0.f) atomicAdd(&g_pos_loss, (double)bpl);
    if (bpw != 0.f) atomicAdd(&g_pos_w, (double)bpw);
    if (bnp) atomicAdd(&g_sumPos, bnp);
  }
  for (int i = threadIdx.x; i < NB; i += THR_H) {
    unsigned cv = hist[i];
    if (cv) atomicAdd(&g_hist32[i], cv);
  }
}

// ---------------------------------------------------------------
// Finalize (1 block, 1024 threads). Fully-coalesced uint4 loads: thread t
// owns a 4-code group in each of 8 segments (codes 4*(t+1024j)..+3).
// Two-level exact descending selection: segment totals -> boundary segment
// -> one u32 block scan for within-segment exclusive "count above" ->
// per-thread full/partial take. Exact: all members of a bin share a value.
__global__ void __launch_bounds__(THR_F) k_final(float* __restrict__ out) {
  __shared__ unsigned scnt_s[NSEG * THR_F];     // 32KB per-thread group counts
  __shared__ double wvs[NSEG][32];              // per-warp value-sum partials
  __shared__ double segVs[NSEG];
  __shared__ u64 segCnt[NSEG];
  __shared__ unsigned sExcl[THR_F];
  __shared__ unsigned wpart[32];
  __shared__ double dred[32];
  __shared__ int s_bs;
  __shared__ long long s_r, s_K;
  __shared__ double s_full;
  const int t = threadIdx.x;
  const unsigned lane = t & 31u, wid = t >> 5;
  const uint4* h4 = (const uint4*)g_hist32;
#pragma unroll
  for (int j = 0; j < NSEG; j++) {
    uint4 q = h4[t + THR_F * j];
    unsigned cj = q.x + q.y + q.z + q.w;
    scnt_s[j * THR_F + t] = cj;
    unsigned cbase = 4u * (unsigned)(t + THR_F * j);
    double vj = (double)q.x * (double)bf2fs(cbase)
              + (double)q.y * (double)bf2fs(cbase + 1)
              + (double)q.z * (double)bf2fs(cbase + 2)
              + (double)q.w * (double)bf2fs(cbase + 3);
    for (int o = 16; o; o >>= 1)
      vj += __shfl_down_sync(0xffffffffu, vj, o);
    if (lane == 0u) wvs[j][wid] = vj;
  }
  __syncthreads();
  // segment totals: warp j (j<8) reduces segment j
  if (wid < NSEG) {
    int j = wid;
    double v = wvs[j][lane];
    u64 cc = 0ull;
#pragma unroll
    for (int m = 0; m < 32; m++) cc += scnt_s[j * THR_F + lane + 32 * m];
    for (int o = 16; o; o >>= 1) {
      v  += __shfl_down_sync(0xffffffffu, v, o);
      cc += __shfl_down_sync(0xffffffffu, cc, o);
    }
    if (lane == 0u) { segVs[j] = v; segCnt[j] = cc; }
  }
  __syncthreads();
  if (t == 0) {
    long long sp = (long long)g_sumPos;
    long long K = 3 * sp;
    long long sn = (long long)NPIX - sp;
    if (K > sn) K = sn;
    s_K = K;
    long long cum = 0;
    double full = 0.0;
    int bs = 0; long long r = 0;
    for (int j = NSEG - 1; j >= 0; j--) {
      if (cum + (long long)segCnt[j] >= K) { bs = j; r = K - cum; break; }
      cum += (long long)segCnt[j];
      full += segVs[j];
    }
    s_bs = bs; s_r = r; s_full = full;
  }
  __syncthreads();
  const int bs = s_bs;
  const long long r = s_r;
  // block inclusive scan of reversed counts -> exclusive "count above group"
  unsigned y = scnt_s[bs * THR_F + (THR_F - 1 - t)];
  unsigned incl = y;
  for (int o = 1; o < 32; o <<= 1) {
    unsigned v = __shfl_up_sync(0xffffffffu, incl, o);
    if (lane >= o) incl += v;
  }
  if (lane == 31u) wpart[wid] = incl;
  __syncthreads();
  if (wid == 0) {
    unsigned wv = wpart[lane];
    unsigned wi = wv;
    for (int o = 1; o < 32; o <<= 1) {
      unsigned x = __shfl_up_sync(0xffffffffu, wi, o);
      if (lane >= o) wi += x;
    }
    wpart[lane] = wi - wv;
  }
  __syncthreads();
  sExcl[THR_F - 1 - t] = wpart[wid] + incl - y;   // count of codes strictly above group
  __syncthreads();
  // per-thread take from its own group in the boundary segment
  double acc = 0.0;
  {
    long long need = r - (long long)sExcl[t];
    if (need > 0) {
      uint4 q = h4[t + THR_F * bs];               // warm L2, coalesced
      unsigned cbase = 4u * (unsigned)(t + THR_F * bs);
      unsigned cd[4] = {q.w, q.z, q.y, q.x};      // descending code order
#pragma unroll
      for (int m = 0; m < 4; m++) {
        if (need <= 0) break;
        long long take = ((long long)cd[m] <= need) ? (long long)cd[m] : need;
        if (take > 0)
          acc += (double)bf2fs(cbase + 3 - m) * (double)take;
        need -= take;
      }
    }
  }
  for (int o = 16; o; o >>= 1)
    acc += __shfl_down_sync(0xffffffffu, acc, o);
  if (lane == 0u) dred[wid] = acc;
  __syncthreads();
  if (t == 0) {
    double total = g_pos_loss + s_full;
#pragma unroll
    for (int k = 0; k < 32; k++) total += dred[k];
    double denom = 2.0 * g_pos_w + 2.0 * (double)s_K;
    out[0] = (float)(total / denom / (double)BSZ);
  }
  // ---- self-clean (coalesced) ----
  uint4 z = {0u, 0u, 0u, 0u};
  uint4* h4w = (uint4*)g_hist32;
#pragma unroll
  for (int j = 0; j < NSEG; j++) h4w[t + THR_F * j] = z;
  if (t == 0) { g_pos_loss = 0.0; g_pos_w = 0.0; g_sumPos = 0u; }
}

// ---------------------------------------------------------------
extern "C" void kernel_launch(void* const* d_in, const int* in_sizes, int n_in,
                              void* d_out, int out_size) {
  (void)in_sizes; (void)n_in; (void)out_size;
  const float4* pr = (const float4*)d_in[0];
  const float4* vm = (const float4*)d_in[1];
  const float4* wt = (const float4*)d_in[2];
  float* out = (float*)d_out;
  cudaFuncSetAttribute(k_hist, cudaFuncAttributeMaxDynamicSharedMemorySize, NB * 4);
  k_hist<<<GRID_H, THR_H, NB * 4>>>(pr, vm, wt);
  k_final<<<1, THR_F>>>(out);
}

// round 12
// speedup vs baseline: 1.7079x; 1.7079x over previous
#include <cuda_runtime.h>
#include <cstdint>

#define BSZ 32
#define NPIX 13107200
#define HW4 102400            // float4 units per channel-plane per batch
#define HW8 51200             // 8-pixel chunks per batch
#define NCHUNK 1638400        // NPIX/8 total 8-pixel chunks
#define NB 32768              // full bf16-code histogram (15-bit codes)
#define GRID_H 152            // persistent: 1 block per SM
#define THR_H 768
#define STRIDE_H (GRID_H*THR_H)
#define THR_F 1024
#define NSEG 8                // k_final segments (4096 codes each)

typedef unsigned long long u64;

// -------- device state (zero-init at load; k_final self-cleans) -------
__device__ __align__(16) unsigned int g_hist32[NB];
__device__ double g_pos_loss;
__device__ double g_pos_w;
__device__ unsigned int g_sumPos;

// ---- packed f32x2 helpers ----
__device__ __forceinline__ u64 pk2(float a, float b) {
  u64 r; asm("mov.b64 %0, {%1, %2};" : "=l"(r) : "f"(a), "f"(b)); return r;
}
__device__ __forceinline__ void upk2(u64 v, float& a, float& b) {
  asm("mov.b64 {%0, %1}, %2;" : "=f"(a), "=f"(b) : "l"(v));
}
__device__ __forceinline__ u64 fma2(u64 a, u64 b, u64 c) {
  u64 d; asm("fma.rn.f32x2 %0, %1, %2, %3;" : "=l"(d) : "l"(a), "l"(b), "l"(c)); return d;
}
__device__ __forceinline__ u64 mul2(u64 a, u64 b) {
  u64 d; asm("mul.rn.f32x2 %0, %1, %2;" : "=l"(d) : "l"(a), "l"(b)); return d;
}
__device__ __forceinline__ u64 add2(u64 a, u64 b) {
  u64 d; asm("add.rn.f32x2 %0, %1, %2;" : "=l"(d) : "l"(a), "l"(b)); return d;
}
__device__ __forceinline__ unsigned cvt_bf2(float s0, float s1) {
  unsigned w;
  asm("cvt.rn.satfinite.bf16x2.f32 %0, %1, %2;" : "=r"(w) : "f"(s1), "f"(s0));
  return w;
}
// SAFE bf16-code -> value: inf/NaN codes (>= 0x7F80) map to 0. Counts can
// never land there (cvt is satfinite), so this is exact and keeps the
// unconditional count*value products finite (0 * inf would be NaN).
__device__ __forceinline__ float bf2fs(unsigned code) {
  return (code >= 0x7F80u) ? 0.f : __uint_as_float(code << 16);
}

// ---------------------------------------------------------------
// Single data pass: per-pixel row loss -> bf16 code (positives forced to
// code 0), full 32768-bin count histogram privatized in 128KB dynamic
// smem (1 block/SM, persistent), positive sums block-reduced.
__global__ void __launch_bounds__(THR_H) k_hist(const float4* __restrict__ pr,
                                                const float4* __restrict__ vm,
                                                const float4* __restrict__ wt) {
  extern __shared__ unsigned hist[];          // NB counts
  for (int i = threadIdx.x; i < NB; i += THR_H) hist[i] = 0u;
  __syncthreads();
  const u64 M1 = pk2(-1.f, -1.f);
  u64 pl = 0ull, pw = 0ull;
  unsigned np = 0u;
  for (int c = blockIdx.x * THR_H + threadIdx.x; c < NCHUNK; c += STRIDE_H) {
    int b = c / HW8;
    int i = c - b * HW8;
    int base = 2 * i;
    const float4* prb = pr + (size_t)b * 2 * HW4;
    const float4* vmb = vm + (size_t)b * 2 * HW4;
    const float4* wtb = wt + (size_t)b * HW4;
    float4 p0a = prb[base],       p0b = prb[base + 1];
    float4 p1a = prb[base + HW4], p1b = prb[base + HW4 + 1];
    float4 t0a = vmb[base],       t0b = vmb[base + 1];
    float4 t1a = vmb[base + HW4], t1b = vmb[base + HW4 + 1];
    float4 wa = wtb[base], wb = wtb[base + 1];
    u64 d0 = fma2(pk2(t0a.x, t0a.y), M1, pk2(p0a.x, p0a.y));
    u64 d1 = fma2(pk2(t1a.x, t1a.y), M1, pk2(p1a.x, p1a.y));
    u64 se = fma2(d1, d1, mul2(d0, d0));
    u64 wv = pk2(wa.x, wa.y);
    pl = fma2(se, wv, pl); pw = add2(pw, wv);
    float s0, s1; upk2(se, s0, s1);
    unsigned wA = cvt_bf2(s0, s1);
    if (wa.x > 0.f) { wA &= 0xFFFF0000u; np++; }
    if (wa.y > 0.f) { wA &= 0x0000FFFFu; np++; }
    d0 = fma2(pk2(t0a.z, t0a.w), M1, pk2(p0a.z, p0a.w));
    d1 = fma2(pk2(t1a.z, t1a.w), M1, pk2(p1a.z, p1a.w));
    se = fma2(d1, d1, mul2(d0, d0));
    wv = pk2(wa.z, wa.w);
    pl = fma2(se, wv, pl); pw = add2(pw, wv);
    upk2(se, s0, s1);
    unsigned wB = cvt_bf2(s0, s1);
    if (wa.z > 0.f) { wB &= 0xFFFF0000u; np++; }
    if (wa.w > 0.f) { wB &= 0x0000FFFFu; np++; }
    d0 = fma2(pk2(t0b.x, t0b.y), M1, pk2(p0b.x, p0b.y));
    d1 = fma2(pk2(t1b.x, t1b.y), M1, pk2(p1b.x, p1b.y));
    se = fma2(d1, d1, mul2(d0, d0));
    wv = pk2(wb.x, wb.y);
    pl = fma2(se, wv, pl); pw = add2(pw, wv);
    upk2(se, s0, s1);
    unsigned wC = cvt_bf2(s0, s1);
    if (wb.x > 0.f) { wC &= 0xFFFF0000u; np++; }
    if (wb.y > 0.f) { wC &= 0x0000FFFFu; np++; }
    d0 = fma2(pk2(t0b.z, t0b.w), M1, pk2(p0b.z, p0b.w));
    d1 = fma2(pk2(t1b.z, t1b.w), M1, pk2(p1b.z, p1b.w));
    se = fma2(d1, d1, mul2(d0, d0));
    wv = pk2(wb.z, wb.w);
    pl = fma2(se, wv, pl); pw = add2(pw, wv);
    upk2(se, s0, s1);
    unsigned wD = cvt_bf2(s0, s1);
    if (wb.z > 0.f) { wD &= 0xFFFF0000u; np++; }
    if (wb.w > 0.f) { wD &= 0x0000FFFFu; np++; }
    atomicAdd(&hist[wA & 0xFFFFu], 1u);
    atomicAdd(&hist[wA >> 16], 1u);
    atomicAdd(&hist[wB & 0xFFFFu], 1u);
    atomicAdd(&hist[wB >> 16], 1u);
    atomicAdd(&hist[wC & 0xFFFFu], 1u);
    atomicAdd(&hist[wC >> 16], 1u);
    atomicAdd(&hist[wD & 0xFFFFu], 1u);
    atomicAdd(&hist[wD >> 16], 1u);
  }
  float pl0, pl1, pw0, pw1;
  upk2(pl, pl0, pl1); upk2(pw, pw0, pw1);
  float plf = pl0 + pl1, pwf = pw0 + pw1;
  for (int o = 16; o; o >>= 1) {
    plf += __shfl_down_sync(0xffffffffu, plf, o);
    pwf += __shfl_down_sync(0xffffffffu, pwf, o);
    np  += __shfl_down_sync(0xffffffffu, np, o);
  }
  __shared__ float r_pl[THR_H / 32], r_pw[THR_H / 32];
  __shared__ unsigned r_np[THR_H / 32];
  int wid = threadIdx.x >> 5;
  if ((threadIdx.x & 31u) == 0u) { r_pl[wid] = plf; r_pw[wid] = pwf; r_np[wid] = np; }
  __syncthreads();
  if (threadIdx.x == 0) {
    float bpl = 0.f, bpw = 0.f; unsigned bnp = 0u;
#pragma unroll
    for (int k = 0; k < THR_H / 32; k++) { bpl += r_pl[k]; bpw += r_pw[k]; bnp += r_np[k]; }
    if (bpl != 0.f) atomicAdd(&g_pos_loss, (double)bpl);
    if (bpw != 0.f) atomicAdd(&g_pos_w, (double)bpw);
    if (bnp) atomicAdd(&g_sumPos, bnp);
  }
  for (int i = threadIdx.x; i < NB; i += THR_H) {
    unsigned cv = hist[i];
    if (cv) atomicAdd(&g_hist32[i], cv);
  }
}

// ---------------------------------------------------------------
// Finalize (1 block, 1024 threads). Coalesced uint4 loads; selection logic
// identical to the verified R9 structure, but the BULK arithmetic is float
// (32 FFMA/thread) — FP64 only in the tiny thread-0 accumulation.
__global__ void __launch_bounds__(THR_F) k_final(float* __restrict__ out) {
  __shared__ unsigned scnt_s[NSEG * THR_F];     // 32KB per-thread group counts
  __shared__ float wvs[NSEG][32];               // per-warp float value-sum partials
  __shared__ float segVs[NSEG];
  __shared__ unsigned segCnt[NSEG];             // per-segment counts (<= NPIX < 2^32)
  __shared__ unsigned sExcl[THR_F];
  __shared__ unsigned wpart[32];
  __shared__ double dred[32];
  __shared__ int s_bs;
  __shared__ long long s_r, s_K;
  __shared__ double s_full;
  const int t = threadIdx.x;
  const unsigned lane = t & 31u, wid = t >> 5;
  const uint4* h4 = (const uint4*)g_hist32;
  uint4 q[NSEG];
#pragma unroll
  for (int j = 0; j < NSEG; j++) q[j] = h4[t + THR_F * j];
#pragma unroll
  for (int j = 0; j < NSEG; j++) {
    scnt_s[j * THR_F + t] = q[j].x + q[j].y + q[j].z + q[j].w;
    unsigned cbase = 4u * (unsigned)(t + THR_F * j);
    float vj = fmaf((float)q[j].x, bf2fs(cbase),
               fmaf((float)q[j].y, bf2fs(cbase + 1),
               fmaf((float)q[j].z, bf2fs(cbase + 2),
                    (float)q[j].w * bf2fs(cbase + 3))));
    for (int o = 16; o; o >>= 1)
      vj += __shfl_down_sync(0xffffffffu, vj, o);
    if (lane == 0u) wvs[j][wid] = vj;
  }
  __syncthreads();
  // segment totals: warp j (j<8) reduces segment j
  if (wid < NSEG) {
    int j = wid;
    float v = wvs[j][lane];
    unsigned cc = 0u;
#pragma unroll
    for (int m = 0; m < 32; m++) cc += scnt_s[j * THR_F + lane + 32 * m];
    for (int o = 16; o; o >>= 1) {
      v  += __shfl_down_sync(0xffffffffu, v, o);
      cc += __shfl_down_sync(0xffffffffu, cc, o);
    }
    if (lane == 0u) { segVs[j] = v; segCnt[j] = cc; }
  }
  __syncthreads();
  if (t == 0) {
    long long sp = (long long)g_sumPos;
    long long K = 3 * sp;
    long long sn = (long long)NPIX - sp;
    if (K > sn) K = sn;
    s_K = K;
    long long cum = 0;
    double full = 0.0;
    int bs = 0; long long r = 0;
    for (int j = NSEG - 1; j >= 0; j--) {
      if (cum + (long long)segCnt[j] >= K) { bs = j; r = K - cum; break; }
      cum += (long long)segCnt[j];
      full += (double)segVs[j];
    }
    s_bs = bs; s_r = r; s_full = full;
  }
  __syncthreads();
  const int bs = s_bs;
  const long long r = s_r;
  // block inclusive scan of reversed counts -> exclusive "count above group"
  unsigned y = scnt_s[bs * THR_F + (THR_F - 1 - t)];
  unsigned incl = y;
  for (int o = 1; o < 32; o <<= 1) {
    unsigned v = __shfl_up_sync(0xffffffffu, incl, o);
    if (lane >= o) incl += v;
  }
  if (lane == 31u) wpart[wid] = incl;
  __syncthreads();
  if (wid == 0) {
    unsigned wv = wpart[lane];
    unsigned wi = wv;
    for (int o = 1; o < 32; o <<= 1) {
      unsigned x = __shfl_up_sync(0xffffffffu, wi, o);
      if (lane >= o) wi += x;
    }
    wpart[lane] = wi - wv;
  }
  __syncthreads();
  sExcl[THR_F - 1 - t] = wpart[wid] + incl - y;   // count of codes strictly above group
  __syncthreads();
  // per-thread take from its own group in the boundary segment (float)
  float accf = 0.f;
  {
    long long need = r - (long long)sExcl[t];
    if (need > 0) {
      uint4 qb;
#pragma unroll
      for (int j = 0; j < NSEG; j++) if (j == bs) qb = q[j];
      unsigned cbase = 4u * (unsigned)(t + THR_F * bs);
      unsigned cd[4] = {qb.w, qb.z, qb.y, qb.x};  // descending code order
#pragma unroll
      for (int m = 0; m < 4; m++) {
        if (need <= 0) break;
        long long take = ((long long)cd[m] <= need) ? (long long)cd[m] : need;
        if (take > 0)
          accf = fmaf(bf2fs(cbase + 3 - m), (float)take, accf);
        need -= take;
      }
    }
  }
  for (int o = 16; o; o >>= 1)
    accf += __shfl_down_sync(0xffffffffu, accf, o);
  if (lane == 0u) dred[wid] = (double)accf;
  __syncthreads();
  if (t == 0) {
    double total = g_pos_loss + s_full;
#pragma unroll
    for (int k = 0; k < 32; k++) total += dred[k];
    double denom = 2.0 * g_pos_w + 2.0 * (double)s_K;
    out[0] = (float)(total / denom / (double)BSZ);
  }
  // ---- self-clean (coalesced) ----
  uint4 z = {0u, 0u, 0u, 0u};
  uint4* h4w = (uint4*)g_hist32;
#pragma unroll
  for (int j = 0; j < NSEG; j++) h4w[t + THR_F * j] = z;
  if (t == 0) { g_pos_loss = 0.0; g_pos_w = 0.0; g_sumPos = 0u; }
}

// ---------------------------------------------------------------
extern "C" void kernel_launch(void* const* d_in, const int* in_sizes, int n_in,
                              void* d_out, int out_size) {
  (void)in_sizes; (void)n_in; (void)out_size;
  const float4* pr = (const float4*)d_in[0];
  const float4* vm = (const float4*)d_in[1];
  const float4* wt = (const float4*)d_in[2];
  float* out = (float*)d_out;
  cudaFuncSetAttribute(k_hist, cudaFuncAttributeMaxDynamicSharedMemorySize, NB * 4);
  k_hist<<<GRID_H, THR_H, NB * 4>>>(pr, vm, wt);
  k_final<<<1, THR_F>>>(out);
}

// round 13
// speedup vs baseline: 1.7161x; 1.0048x over previous
#include <cuda_runtime.h>
#include <cstdint>

#define BSZ 32
#define NPIX 13107200
#define HW4 102400            // float4 units per channel-plane per batch
#define HW8 51200             // 8-pixel chunks per batch
#define NCHUNK 1638400        // NPIX/8 total 8-pixel chunks
#define NB 32768              // full bf16-code histogram (15-bit codes)
#define GRID_H 152            // persistent: 1 block per SM
#define THR_H 768
#define STRIDE_H (GRID_H*THR_H)
#define NG 8192               // uint4 groups in histogram
#define TSEG 11               // ceil(NG / THR_H) tail segments

typedef unsigned long long u64;

// -------- device state (zero-init at load; tail self-cleans) -------
__device__ __align__(16) unsigned int g_hist32[NB];
__device__ double g_pos_loss;
__device__ double g_pos_w;
__device__ unsigned int g_sumPos;
__device__ unsigned int g_ctr;

// ---- packed f32x2 helpers ----
__device__ __forceinline__ u64 pk2(float a, float b) {
  u64 r; asm("mov.b64 %0, {%1, %2};" : "=l"(r) : "f"(a), "f"(b)); return r;
}
__device__ __forceinline__ void upk2(u64 v, float& a, float& b) {
  asm("mov.b64 {%0, %1}, %2;" : "=f"(a), "=f"(b) : "l"(v));
}
__device__ __forceinline__ u64 fma2(u64 a, u64 b, u64 c) {
  u64 d; asm("fma.rn.f32x2 %0, %1, %2, %3;" : "=l"(d) : "l"(a), "l"(b), "l"(c)); return d;
}
__device__ __forceinline__ u64 mul2(u64 a, u64 b) {
  u64 d; asm("mul.rn.f32x2 %0, %1, %2;" : "=l"(d) : "l"(a), "l"(b)); return d;
}
__device__ __forceinline__ u64 add2(u64 a, u64 b) {
  u64 d; asm("add.rn.f32x2 %0, %1, %2;" : "=l"(d) : "l"(a), "l"(b)); return d;
}
__device__ __forceinline__ unsigned cvt_bf2(float s0, float s1) {
  unsigned w;
  asm("cvt.rn.satfinite.bf16x2.f32 %0, %1, %2;" : "=r"(w) : "f"(s1), "f"(s0));
  return w;
}
// SAFE bf16-code -> value: inf/NaN codes (>= 0x7F80) map to 0. Counts never
// land there (cvt is satfinite), so this is exact and keeps unconditional
// count*value products finite.
__device__ __forceinline__ float bf2fs(unsigned code) {
  return (code >= 0x7F80u) ? 0.f : __uint_as_float(code << 16);
}

// ---------------------------------------------------------------
// Single kernel: data pass (histogram + positive sums) and, in the LAST
// block to finish, the exact top-K selection over the aggregated
// histogram (reusing the 128KB dynamic smem as scan scratch).
__global__ void __launch_bounds__(THR_H) k_all(const float4* __restrict__ pr,
                                               const float4* __restrict__ vm,
                                               const float4* __restrict__ wt,
                                               float* __restrict__ out) {
  extern __shared__ unsigned hist[];          // NB counts / tail scratch
  for (int i = threadIdx.x; i < NB; i += THR_H) hist[i] = 0u;
  __syncthreads();
  const u64 M1 = pk2(-1.f, -1.f);
  u64 pl = 0ull, pw = 0ull;
  unsigned np = 0u;
  for (int c = blockIdx.x * THR_H + threadIdx.x; c < NCHUNK; c += STRIDE_H) {
    int b = c / HW8;
    int i = c - b * HW8;
    int base = 2 * i;
    const float4* prb = pr + (size_t)b * 2 * HW4;
    const float4* vmb = vm + (size_t)b * 2 * HW4;
    const float4* wtb = wt + (size_t)b * HW4;
    float4 p0a = prb[base],       p0b = prb[base + 1];
    float4 p1a = prb[base + HW4], p1b = prb[base + HW4 + 1];
    float4 t0a = vmb[base],       t0b = vmb[base + 1];
    float4 t1a = vmb[base + HW4], t1b = vmb[base + HW4 + 1];
    float4 wa = wtb[base], wb = wtb[base + 1];
    u64 d0 = fma2(pk2(t0a.x, t0a.y), M1, pk2(p0a.x, p0a.y));
    u64 d1 = fma2(pk2(t1a.x, t1a.y), M1, pk2(p1a.x, p1a.y));
    u64 se = fma2(d1, d1, mul2(d0, d0));
    u64 wv = pk2(wa.x, wa.y);
    pl = fma2(se, wv, pl); pw = add2(pw, wv);
    float s0, s1; upk2(se, s0, s1);
    unsigned wA = cvt_bf2(s0, s1);
    if (wa.x > 0.f) { wA &= 0xFFFF0000u; np++; }
    if (wa.y > 0.f) { wA &= 0x0000FFFFu; np++; }
    d0 = fma2(pk2(t0a.z, t0a.w), M1, pk2(p0a.z, p0a.w));
    d1 = fma2(pk2(t1a.z, t1a.w), M1, pk2(p1a.z, p1a.w));
    se = fma2(d1, d1, mul2(d0, d0));
    wv = pk2(wa.z, wa.w);
    pl = fma2(se, wv, pl); pw = add2(pw, wv);
    upk2(se, s0, s1);
    unsigned wB = cvt_bf2(s0, s1);
    if (wa.z > 0.f) { wB &= 0xFFFF0000u; np++; }
    if (wa.w > 0.f) { wB &= 0x0000FFFFu; np++; }
    d0 = fma2(pk2(t0b.x, t0b.y), M1, pk2(p0b.x, p0b.y));
    d1 = fma2(pk2(t1b.x, t1b.y), M1, pk2(p1b.x, p1b.y));
    se = fma2(d1, d1, mul2(d0, d0));
    wv = pk2(wb.x, wb.y);
    pl = fma2(se, wv, pl); pw = add2(pw, wv);
    upk2(se, s0, s1);
    unsigned wC = cvt_bf2(s0, s1);
    if (wb.x > 0.f) { wC &= 0xFFFF0000u; np++; }
    if (wb.y > 0.f) { wC &= 0x0000FFFFu; np++; }
    d0 = fma2(pk2(t0b.z, t0b.w), M1, pk2(p0b.z, p0b.w));
    d1 = fma2(pk2(t1b.z, t1b.w), M1, pk2(p1b.z, p1b.w));
    se = fma2(d1, d1, mul2(d0, d0));
    wv = pk2(wb.z, wb.w);
    pl = fma2(se, wv, pl); pw = add2(pw, wv);
    upk2(se, s0, s1);
    unsigned wD = cvt_bf2(s0, s1);
    if (wb.z > 0.f) { wD &= 0xFFFF0000u; np++; }
    if (wb.w > 0.f) { wD &= 0x0000FFFFu; np++; }
    atomicAdd(&hist[wA & 0xFFFFu], 1u);
    atomicAdd(&hist[wA >> 16], 1u);
    atomicAdd(&hist[wB & 0xFFFFu], 1u);
    atomicAdd(&hist[wB >> 16], 1u);
    atomicAdd(&hist[wC & 0xFFFFu], 1u);
    atomicAdd(&hist[wC >> 16], 1u);
    atomicAdd(&hist[wD & 0xFFFFu], 1u);
    atomicAdd(&hist[wD >> 16], 1u);
  }
  float pl0, pl1, pw0, pw1;
  upk2(pl, pl0, pl1); upk2(pw, pw0, pw1);
  float plf = pl0 + pl1, pwf = pw0 + pw1;
  for (int o = 16; o; o >>= 1) {
    plf += __shfl_down_sync(0xffffffffu, plf, o);
    pwf += __shfl_down_sync(0xffffffffu, pwf, o);
    np  += __shfl_down_sync(0xffffffffu, np, o);
  }
  __shared__ float r_pl[THR_H / 32], r_pw[THR_H / 32];
  __shared__ unsigned r_np[THR_H / 32];
  const int t = threadIdx.x;
  const unsigned lane = t & 31u, wid = t >> 5;
  if (lane == 0u) { r_pl[wid] = plf; r_pw[wid] = pwf; r_np[wid] = np; }
  __syncthreads();
  if (t == 0) {
    float bpl = 0.f, bpw = 0.f; unsigned bnp = 0u;
#pragma unroll
    for (int k = 0; k < THR_H / 32; k++) { bpl += r_pl[k]; bpw += r_pw[k]; bnp += r_np[k]; }
    if (bpl != 0.f) atomicAdd(&g_pos_loss, (double)bpl);
    if (bpw != 0.f) atomicAdd(&g_pos_w, (double)bpw);
    if (bnp) atomicAdd(&g_sumPos, bnp);
  }
  for (int i = t; i < NB; i += THR_H) {
    unsigned cv = hist[i];
    if (cv) atomicAdd(&g_hist32[i], cv);
  }
  // ================= last-block-done tail =================
  __shared__ int s_last;
  __threadfence();
  if (t == 0) s_last = (atomicAdd(&g_ctr, 1u) == GRID_H - 1u);
  __syncthreads();
  if (!s_last) return;
  __threadfence();
  // dynamic smem is dead (hist flushed): reuse as tail scratch
  unsigned* scnt = hist;                        // [TSEG * THR_H]
  unsigned* sExcl = hist + TSEG * THR_H;        // [THR_H]
  __shared__ float wvs[TSEG][THR_H / 32];
  __shared__ float segVs[TSEG];
  __shared__ unsigned segCnt[TSEG];
  __shared__ unsigned wpart[THR_H / 32];
  __shared__ double dred[THR_H / 32];
  __shared__ int s_bs;
  __shared__ long long s_r, s_K;
  __shared__ double s_full;
  const uint4* h4 = (const uint4*)g_hist32;
  // phase 1: per-group counts + float value-sums (warm L2, coalesced)
#pragma unroll
  for (int j = 0; j < TSEG; j++) {
    int g = j * THR_H + t;
    uint4 q = (g < NG) ? h4[g] : make_uint4(0u, 0u, 0u, 0u);
    scnt[j * THR_H + t] = q.x + q.y + q.z + q.w;
    unsigned cbase = 4u * (unsigned)g;
    float vj = (g < NG)
      ? fmaf((float)q.x, bf2fs(cbase),
        fmaf((float)q.y, bf2fs(cbase + 1),
        fmaf((float)q.z, bf2fs(cbase + 2),
             (float)q.w * bf2fs(cbase + 3))))
      : 0.f;
    for (int o = 16; o; o >>= 1)
      vj += __shfl_down_sync(0xffffffffu, vj, o);
    if (lane == 0u) wvs[j][wid] = vj;
  }
  __syncthreads();
  // phase 2: segment totals (warp j reduces segment j)
  if (wid < TSEG) {
    int j = wid;
    float v = (lane < THR_H / 32) ? wvs[j][lane] : 0.f;
    unsigned cc = 0u;
#pragma unroll
    for (int m = 0; m < 24; m++) cc += scnt[j * THR_H + lane * 24 + m];
    for (int o = 16; o; o >>= 1) {
      v  += __shfl_down_sync(0xffffffffu, v, o);
      cc += __shfl_down_sync(0xffffffffu, cc, o);
    }
    if (lane == 0u) { segVs[j] = v; segCnt[j] = cc; }
  }
  __syncthreads();
  // phase 3: boundary segment (thread 0, tiny FP64)
  if (t == 0) {
    long long sp = (long long)g_sumPos;
    long long K = 3 * sp;
    long long sn = (long long)NPIX - sp;
    if (K > sn) K = sn;
    s_K = K;
    long long cum = 0;
    double full = 0.0;
    int bs = 0; long long r = 0;
    for (int j = TSEG - 1; j >= 0; j--) {
      if (cum + (long long)segCnt[j] >= K) { bs = j; r = K - cum; break; }
      cum += (long long)segCnt[j];
      full += (double)segVs[j];
    }
    s_bs = bs; s_r = r; s_full = full;
  }
  __syncthreads();
  const int bs = s_bs;
  const long long r = s_r;
  // phase 4: reversed block scan -> exclusive "count above group"
  unsigned y = scnt[bs * THR_H + (THR_H - 1 - t)];
  unsigned incl = y;
  for (int o = 1; o < 32; o <<= 1) {
    unsigned v = __shfl_up_sync(0xffffffffu, incl, o);
    if (lane >= o) incl += v;
  }
  if (lane == 31u) wpart[wid] = incl;
  __syncthreads();
  if (wid == 0) {
    unsigned wv = (lane < THR_H / 32) ? wpart[lane] : 0u;
    unsigned wi = wv;
    for (int o = 1; o < 32; o <<= 1) {
      unsigned x = __shfl_up_sync(0xffffffffu, wi, o);
      if (lane >= o) wi += x;
    }
    if (lane < THR_H / 32) wpart[lane] = wi - wv;
  }
  __syncthreads();
  sExcl[THR_H - 1 - t] = wpart[wid] + incl - y;
  __syncthreads();
  // phase 5: per-thread take from boundary segment (float)
  float accf = 0.f;
  {
    int g = bs * THR_H + t;
    long long need = r - (long long)sExcl[t];
    if (need > 0 && g < NG) {
      uint4 qb = h4[g];
      unsigned cbase = 4u * (unsigned)g;
      unsigned cd[4] = {qb.w, qb.z, qb.y, qb.x};
#pragma unroll
      for (int m = 0; m < 4; m++) {
        if (need <= 0) break;
        long long take = ((long long)cd[m] <= need) ? (long long)cd[m] : need;
        if (take > 0)
          accf = fmaf(bf2fs(cbase + 3 - m), (float)take, accf);
        need -= take;
      }
    }
  }
  for (int o = 16; o; o >>= 1)
    accf += __shfl_down_sync(0xffffffffu, accf, o);
  if (lane == 0u) dred[wid] = (double)accf;
  __syncthreads();
  if (t == 0) {
    double total = g_pos_loss + s_full;
#pragma unroll
    for (int k = 0; k < THR_H / 32; k++) total += dred[k];
    double denom = 2.0 * g_pos_w + 2.0 * (double)s_K;
    out[0] = (float)(total / denom / (double)BSZ);
  }
  // phase 6: self-clean for next replay
  uint4 z = {0u, 0u, 0u, 0u};
  uint4* h4w = (uint4*)g_hist32;
#pragma unroll
  for (int j = 0; j < TSEG; j++) {
    int g = j * THR_H + t;
    if (g < NG) h4w[g] = z;
  }
  if (t == 0) {
    g_pos_loss = 0.0; g_pos_w = 0.0; g_sumPos = 0u; g_ctr = 0u;
  }
}

// ---------------------------------------------------------------
extern "C" void kernel_launch(void* const* d_in, const int* in_sizes, int n_in,
                              void* d_out, int out_size) {
  (void)in_sizes; (void)n_in; (void)out_size;
  const float4* pr = (const float4*)d_in[0];
  const float4* vm = (const float4*)d_in[1];
  const float4* wt = (const float4*)d_in[2];
  float* out = (float*)d_out;
  cudaFuncSetAttribute(k_all, cudaFuncAttributeMaxDynamicSharedMemorySize, NB * 4);
  k_all<<<GRID_H, THR_H, NB * 4>>>(pr, vm, wt, out);
}

// round 14
// speedup vs baseline: 1.7171x; 1.0006x over previous
#include <cuda_runtime.h>
#include <cstdint>

#define BSZ 32
#define NPIX 13107200
#define HW4 102400            // float4 units per channel-plane per batch
#define HW8 51200             // 8-pixel chunks per batch
#define NCHUNK 1638400        // NPIX/8 total 8-pixel chunks
#define NB 32768              // full bf16-code histogram (15-bit codes)
#define GRID_H 152            // persistent: 1 block per SM
#define THR_H 1024
#define STRIDE_H (GRID_H*THR_H)
#define NG 8192               // uint4 groups in histogram
#define TSEG 8                // NG / THR_H tail segments (exact)
#define NW (THR_H/32)         // 32 warps

typedef unsigned long long u64;

// -------- device state (zero-init at load; tail self-cleans) -------
__device__ __align__(16) unsigned int g_hist32[NB];
__device__ double g_pos_loss;
__device__ double g_pos_w;
__device__ unsigned int g_sumPos;
__device__ unsigned int g_ctr;

// ---- packed f32x2 helpers ----
__device__ __forceinline__ u64 pk2(float a, float b) {
  u64 r; asm("mov.b64 %0, {%1, %2};" : "=l"(r) : "f"(a), "f"(b)); return r;
}
__device__ __forceinline__ void upk2(u64 v, float& a, float& b) {
  asm("mov.b64 {%0, %1}, %2;" : "=f"(a), "=f"(b) : "l"(v));
}
__device__ __forceinline__ u64 fma2(u64 a, u64 b, u64 c) {
  u64 d; asm("fma.rn.f32x2 %0, %1, %2, %3;" : "=l"(d) : "l"(a), "l"(b), "l"(c)); return d;
}
__device__ __forceinline__ u64 mul2(u64 a, u64 b) {
  u64 d; asm("mul.rn.f32x2 %0, %1, %2;" : "=l"(d) : "l"(a), "l"(b)); return d;
}
__device__ __forceinline__ u64 add2(u64 a, u64 b) {
  u64 d; asm("add.rn.f32x2 %0, %1, %2;" : "=l"(d) : "l"(a), "l"(b)); return d;
}
__device__ __forceinline__ unsigned cvt_bf2(float s0, float s1) {
  unsigned w;
  asm("cvt.rn.satfinite.bf16x2.f32 %0, %1, %2;" : "=r"(w) : "f"(s1), "f"(s0));
  return w;
}
// SAFE bf16-code -> value: inf/NaN codes (>= 0x7F80) map to 0. Counts never
// land there (cvt is satfinite), so this is exact and keeps unconditional
// count*value products finite.
__device__ __forceinline__ float bf2fs(unsigned code) {
  return (code >= 0x7F80u) ? 0.f : __uint_as_float(code << 16);
}

// ---------------------------------------------------------------
// Single kernel: data pass (histogram + positive sums) and, in the LAST
// block to finish, the exact top-K selection over the aggregated
// histogram (reusing the 128KB dynamic smem as scan scratch).
__global__ void __launch_bounds__(THR_H) k_all(const float4* __restrict__ pr,
                                               const float4* __restrict__ vm,
                                               const float4* __restrict__ wt,
                                               float* __restrict__ out) {
  extern __shared__ unsigned hist[];          // NB counts / tail scratch
  for (int i = threadIdx.x; i < NB; i += THR_H) hist[i] = 0u;
  __syncthreads();
  const u64 M1 = pk2(-1.f, -1.f);
  u64 pl = 0ull, pw = 0ull;
  unsigned np = 0u;
  for (int c = blockIdx.x * THR_H + threadIdx.x; c < NCHUNK; c += STRIDE_H) {
    int b = c / HW8;
    int i = c - b * HW8;
    int base = 2 * i;
    const float4* prb = pr + (size_t)b * 2 * HW4;
    const float4* vmb = vm + (size_t)b * 2 * HW4;
    const float4* wtb = wt + (size_t)b * HW4;
    float4 p0a = prb[base],       p0b = prb[base + 1];
    float4 p1a = prb[base + HW4], p1b = prb[base + HW4 + 1];
    float4 t0a = vmb[base],       t0b = vmb[base + 1];
    float4 t1a = vmb[base + HW4], t1b = vmb[base + HW4 + 1];
    float4 wa = wtb[base], wb = wtb[base + 1];
    u64 d0 = fma2(pk2(t0a.x, t0a.y), M1, pk2(p0a.x, p0a.y));
    u64 d1 = fma2(pk2(t1a.x, t1a.y), M1, pk2(p1a.x, p1a.y));
    u64 se = fma2(d1, d1, mul2(d0, d0));
    u64 wv = pk2(wa.x, wa.y);
    pl = fma2(se, wv, pl); pw = add2(pw, wv);
    float s0, s1; upk2(se, s0, s1);
    unsigned wA = cvt_bf2(s0, s1);
    if (wa.x > 0.f) { wA &= 0xFFFF0000u; np++; }
    if (wa.y > 0.f) { wA &= 0x0000FFFFu; np++; }
    d0 = fma2(pk2(t0a.z, t0a.w), M1, pk2(p0a.z, p0a.w));
    d1 = fma2(pk2(t1a.z, t1a.w), M1, pk2(p1a.z, p1a.w));
    se = fma2(d1, d1, mul2(d0, d0));
    wv = pk2(wa.z, wa.w);
    pl = fma2(se, wv, pl); pw = add2(pw, wv);
    upk2(se, s0, s1);
    unsigned wB = cvt_bf2(s0, s1);
    if (wa.z > 0.f) { wB &= 0xFFFF0000u; np++; }
    if (wa.w > 0.f) { wB &= 0x0000FFFFu; np++; }
    d0 = fma2(pk2(t0b.x, t0b.y), M1, pk2(p0b.x, p0b.y));
    d1 = fma2(pk2(t1b.x, t1b.y), M1, pk2(p1b.x, p1b.y));
    se = fma2(d1, d1, mul2(d0, d0));
    wv = pk2(wb.x, wb.y);
    pl = fma2(se, wv, pl); pw = add2(pw, wv);
    upk2(se, s0, s1);
    unsigned wC = cvt_bf2(s0, s1);
    if (wb.x > 0.f) { wC &= 0xFFFF0000u; np++; }
    if (wb.y > 0.f) { wC &= 0x0000FFFFu; np++; }
    d0 = fma2(pk2(t0b.z, t0b.w), M1, pk2(p0b.z, p0b.w));
    d1 = fma2(pk2(t1b.z, t1b.w), M1, pk2(p1b.z, p1b.w));
    se = fma2(d1, d1, mul2(d0, d0));
    wv = pk2(wb.z, wb.w);
    pl = fma2(se, wv, pl); pw = add2(pw, wv);
    upk2(se, s0, s1);
    unsigned wD = cvt_bf2(s0, s1);
    if (wb.z > 0.f) { wD &= 0xFFFF0000u; np++; }
    if (wb.w > 0.f) { wD &= 0x0000FFFFu; np++; }
    atomicAdd(&hist[wA & 0xFFFFu], 1u);
    atomicAdd(&hist[wA >> 16], 1u);
    atomicAdd(&hist[wB & 0xFFFFu], 1u);
    atomicAdd(&hist[wB >> 16], 1u);
    atomicAdd(&hist[wC & 0xFFFFu], 1u);
    atomicAdd(&hist[wC >> 16], 1u);
    atomicAdd(&hist[wD & 0xFFFFu], 1u);
    atomicAdd(&hist[wD >> 16], 1u);
  }
  float pl0, pl1, pw0, pw1;
  upk2(pl, pl0, pl1); upk2(pw, pw0, pw1);
  float plf = pl0 + pl1, pwf = pw0 + pw1;
  for (int o = 16; o; o >>= 1) {
    plf += __shfl_down_sync(0xffffffffu, plf, o);
    pwf += __shfl_down_sync(0xffffffffu, pwf, o);
    np  += __shfl_down_sync(0xffffffffu, np, o);
  }
  __shared__ float r_pl[NW], r_pw[NW];
  __shared__ unsigned r_np[NW];
  const int t = threadIdx.x;
  const unsigned lane = t & 31u, wid = t >> 5;
  if (lane == 0u) { r_pl[wid] = plf; r_pw[wid] = pwf; r_np[wid] = np; }
  __syncthreads();
  if (t == 0) {
    float bpl = 0.f, bpw = 0.f; unsigned bnp = 0u;
#pragma unroll
    for (int k = 0; k < NW; k++) { bpl += r_pl[k]; bpw += r_pw[k]; bnp += r_np[k]; }
    if (bpl != 0.f) atomicAdd(&g_pos_loss, (double)bpl);
    if (bpw != 0.f) atomicAdd(&g_pos_w, (double)bpw);
    if (bnp) atomicAdd(&g_sumPos, bnp);
  }
  for (int i = t; i < NB; i += THR_H) {
    unsigned cv = hist[i];
    if (cv) atomicAdd(&g_hist32[i], cv);
  }
  // ================= last-block-done tail =================
  __shared__ int s_last;
  __threadfence();
  if (t == 0) s_last = (atomicAdd(&g_ctr, 1u) == GRID_H - 1u);
  __syncthreads();
  if (!s_last) return;
  __threadfence();
  // dynamic smem is dead (hist flushed): reuse as tail scratch
  unsigned* scnt = hist;                        // [TSEG * THR_H]
  unsigned* sExcl = hist + TSEG * THR_H;        // [THR_H]
  __shared__ float wvs[TSEG][NW];
  __shared__ float segVs[TSEG];
  __shared__ unsigned segCnt[TSEG];
  __shared__ unsigned wpart[NW];
  __shared__ double dred[NW];
  __shared__ int s_bs;
  __shared__ long long s_r, s_K;
  __shared__ double s_full;
  const uint4* h4 = (const uint4*)g_hist32;
  // phase 1: per-group counts + float value-sums (warm L2, coalesced)
#pragma unroll
  for (int j = 0; j < TSEG; j++) {
    int g = j * THR_H + t;
    uint4 q = h4[g];
    scnt[j * THR_H + t] = q.x + q.y + q.z + q.w;
    unsigned cbase = 4u * (unsigned)g;
    float vj = fmaf((float)q.x, bf2fs(cbase),
               fmaf((float)q.y, bf2fs(cbase + 1),
               fmaf((float)q.z, bf2fs(cbase + 2),
                    (float)q.w * bf2fs(cbase + 3))));
    for (int o = 16; o; o >>= 1)
      vj += __shfl_down_sync(0xffffffffu, vj, o);
    if (lane == 0u) wvs[j][wid] = vj;
  }
  __syncthreads();
  // phase 2: segment totals (warp j reduces segment j; conflict-free reads)
  if (wid < TSEG) {
    int j = wid;
    float v = wvs[j][lane];
    unsigned cc = 0u;
#pragma unroll
    for (int m = 0; m < THR_H / 32; m++) cc += scnt[j * THR_H + lane + 32 * m];
    for (int o = 16; o; o >>= 1) {
      v  += __shfl_down_sync(0xffffffffu, v, o);
      cc += __shfl_down_sync(0xffffffffu, cc, o);
    }
    if (lane == 0u) { segVs[j] = v; segCnt[j] = cc; }
  }
  __syncthreads();
  // phase 3: boundary segment (thread 0, tiny FP64)
  if (t == 0) {
    long long sp = (long long)g_sumPos;
    long long K = 3 * sp;
    long long sn = (long long)NPIX - sp;
    if (K > sn) K = sn;
    s_K = K;
    long long cum = 0;
    double full = 0.0;
    int bs = 0; long long r = 0;
    for (int j = TSEG - 1; j >= 0; j--) {
      if (cum + (long long)segCnt[j] >= K) { bs = j; r = K - cum; break; }
      cum += (long long)segCnt[j];
      full += (double)segVs[j];
    }
    s_bs = bs; s_r = r; s_full = full;
  }
  __syncthreads();
  const int bs = s_bs;
  const long long r = s_r;
  // phase 4: reversed block scan -> exclusive "count above group"
  unsigned y = scnt[bs * THR_H + (THR_H - 1 - t)];
  unsigned incl = y;
  for (int o = 1; o < 32; o <<= 1) {
    unsigned v = __shfl_up_sync(0xffffffffu, incl, o);
    if (lane >= o) incl += v;
  }
  if (lane == 31u) wpart[wid] = incl;
  __syncthreads();
  if (wid == 0) {
    unsigned wv = wpart[lane];
    unsigned wi = wv;
    for (int o = 1; o < 32; o <<= 1) {
      unsigned x = __shfl_up_sync(0xffffffffu, wi, o);
      if (lane >= o) wi += x;
    }
    wpart[lane] = wi - wv;
  }
  __syncthreads();
  sExcl[THR_H - 1 - t] = wpart[wid] + incl - y;
  __syncthreads();
  // phase 5: per-thread take from boundary segment (float)
  float accf = 0.f;
  {
    int g = bs * THR_H + t;
    long long need = r - (long long)sExcl[t];
    if (need > 0) {
      uint4 qb = h4[g];
      unsigned cbase = 4u * (unsigned)g;
      unsigned cd[4] = {qb.w, qb.z, qb.y, qb.x};
#pragma unroll
      for (int m = 0; m < 4; m++) {
        if (need <= 0) break;
        long long take = ((long long)cd[m] <= need) ? (long long)cd[m] : need;
        if (take > 0)
          accf = fmaf(bf2fs(cbase + 3 - m), (float)take, accf);
        need -= take;
      }
    }
  }
  for (int o = 16; o; o >>= 1)
    accf += __shfl_down_sync(0xffffffffu, accf, o);
  if (lane == 0u) dred[wid] = (double)accf;
  __syncthreads();
  if (t == 0) {
    double total = g_pos_loss + s_full;
#pragma unroll
    for (int k = 0; k < NW; k++) total += dred[k];
    double denom = 2.0 * g_pos_w + 2.0 * (double)s_K;
    out[0] = (float)(total / denom / (double)BSZ);
  }
  // phase 6: self-clean for next replay
  uint4 z = {0u, 0u, 0u, 0u};
  uint4* h4w = (uint4*)g_hist32;
#pragma unroll
  for (int j = 0; j < TSEG; j++) h4w[j * THR_H + t] = z;
  if (t == 0) {
    g_pos_loss = 0.0; g_pos_w = 0.0; g_sumPos = 0u; g_ctr = 0u;
  }
}

// ---------------------------------------------------------------
extern "C" void kernel_launch(void* const* d_in, const int* in_sizes, int n_in,
                              void* d_out, int out_size) {
  (void)in_sizes; (void)n_in; (void)out_size;
  const float4* pr = (const float4*)d_in[0];
  const float4* vm = (const float4*)d_in[1];
  const float4* wt = (const float4*)d_in[2];
  float* out = (float*)d_out;
  cudaFuncSetAttribute(k_all, cudaFuncAttributeMaxDynamicSharedMemorySize, NB * 4);
  k_all<<<GRID_H, THR_H, NB * 4>>>(pr, vm, wt, out);
}